// round 15
// baseline (speedup 1.0000x reference)
#include <cuda_runtime.h>
#include <cuda_bf16.h>
#include <stdint.h>

// MinibatchDiscrimination, warp-specialized fused kernel.
// Producer warps 0-7: bf16 mma.sync GEMM (cp.async T stream) -> Ms[2] smem buffers.
// Consumer warps 8-15: x->out copy + pairwise L1 (bf16x2) + guarded exp.

#define NSAMP   16384
#define FDIM    256
#define NCOLS   512
#define NK      32
#define KD      16
#define OUTF    288
#define SPB     64
#define SSP     32            // samples per subtile
#define NBLK    (NSAMP/SPB)   // 256
#define NT      512
#define KC      32
#define NCH     8             // chunks per subtile
#define NCHT    16            // total chunk iterations (2 subtiles)
#define NBUF    3

#define XST 264
#define TST 520
#define MST 520
#define XS_OFF 0
#define MS_OFF (SSP*XST)               // 8448 halfs
#define MSBUF  (SSP*MST)               // 16640 halfs
#define TS_OFF (MS_OFF + 2*MSBUF)      // 41728
#define TSBUF  (KC*TST)                // 16640
#define SMEM_HALFS (TS_OFF + NBUF*TSBUF)  // 91648
#define SMEM_BYTES (SMEM_HALFS*2)         // 183296 B -> 1 CTA/SM

__device__ __nv_bfloat16 g_Tbf[FDIM * NCOLS];   // 256 KB

__global__ void convT_kernel(const float* __restrict__ T) {
    int i = blockIdx.x * blockDim.x + threadIdx.x;   // float4 index
    #pragma unroll
    for (int j = 0; j < 2; j++) {
        float4 v = ((const float4*)T)[i + j * 16384];
        *(__nv_bfloat162*)&g_Tbf[(i + j * 16384) * 4]     = __floats2bfloat162_rn(v.x, v.y);
        *(__nv_bfloat162*)&g_Tbf[(i + j * 16384) * 4 + 2] = __floats2bfloat162_rn(v.z, v.w);
    }
}

__device__ __forceinline__ unsigned int smem_addr(const void* p) {
    return (unsigned int)__cvta_generic_to_shared(p);
}
__device__ __forceinline__ void cp16(unsigned int dst, const void* src) {
    asm volatile("cp.async.cg.shared.global [%0], [%1], 16;" :: "r"(dst), "l"(src));
}
__device__ __forceinline__ void ldmatrix_x4(unsigned int* r, unsigned int addr) {
    asm volatile("ldmatrix.sync.aligned.m8n8.x4.shared.b16 {%0,%1,%2,%3}, [%4];"
                 : "=r"(r[0]), "=r"(r[1]), "=r"(r[2]), "=r"(r[3]) : "r"(addr));
}
__device__ __forceinline__ void ldmatrix_x4_trans(unsigned int* r, unsigned int addr) {
    asm volatile("ldmatrix.sync.aligned.m8n8.x4.trans.shared.b16 {%0,%1,%2,%3}, [%4];"
                 : "=r"(r[0]), "=r"(r[1]), "=r"(r[2]), "=r"(r[3]) : "r"(addr));
}
__device__ __forceinline__ void mma_bf16(float* c, const unsigned int* a, const unsigned int* b) {
    asm volatile("mma.sync.aligned.m16n8k16.row.col.f32.bf16.bf16.f32 "
                 "{%0,%1,%2,%3}, {%4,%5,%6,%7}, {%8,%9}, {%0,%1,%2,%3};"
                 : "+f"(c[0]), "+f"(c[1]), "+f"(c[2]), "+f"(c[3])
                 : "r"(a[0]), "r"(a[1]), "r"(a[2]), "r"(a[3]), "r"(b[0]), "r"(b[1]));
}
__device__ __forceinline__ void bar_sync(int id, int cnt) {
    asm volatile("bar.sync %0, %1;" :: "r"(id), "r"(cnt) : "memory");
}
__device__ __forceinline__ void bar_arrive(int id, int cnt) {
    asm volatile("bar.arrive %0, %1;" :: "r"(id), "r"(cnt) : "memory");
}

extern __shared__ __nv_bfloat16 sm[];

__global__ void __launch_bounds__(NT, 1) mbd_kernel(
    const float* __restrict__ x,
    float* __restrict__ out)
{
    __nv_bfloat16* xs = sm + XS_OFF;
    const int t = threadIdx.x;
    const int warp = t >> 5;
    const int lane = t & 31;
    const long sbase = (long)blockIdx.x * SPB;

    if (warp < 8) {
        // ================= PRODUCER =================
        const int pw = warp;
        const int wm = pw & 1;            // m-half of 32-sample subtile
        const int wn = pw >> 1;           // n-quarter: cols wn*128..+127
        const int arow = lane & 15;
        const int acg  = lane >> 4;
        const int brow_in = ((lane >> 3) & 1) * 8 + (lane & 7);
        const int bcol_in = (lane >> 4) * 8;

        // prefetch T chunks gc=0,1 (2048 granules each; 8/thread over 256 prod threads)
        #pragma unroll
        for (int c = 0; c < 2; c++) {
            const char* src = (const char*)(g_Tbf + (long)c * KC * NCOLS);
            unsigned int dst = smem_addr(sm + TS_OFF + c * TSBUF);
            #pragma unroll
            for (int i = 0; i < 8; i++) {
                int g = t + i * 256;
                int r = g >> 6, c16 = g & 63;
                cp16(dst + (r * TST + c16 * 8) * 2, src + r * 1024 + c16 * 16);
            }
            asm volatile("cp.async.commit_group;");
        }

        #pragma unroll 1
        for (int sub = 0; sub < 2; sub++) {
            bar_sync(3, 256);   // all producers done reading xs of previous subtile

            // stage xs: 32 samples x 64 float4 = 2048 over 256 thr = 8/thread (PRMT trunc)
            {
                const float4* xg = (const float4*)(x + (sbase + sub * SSP) * FDIM);
                #pragma unroll
                for (int i = 0; i < 8; i++) {
                    int idx = t + i * 256;
                    int s = idx >> 6, c4 = idx & 63;
                    float4 v = xg[idx];
                    unsigned int p0 = __byte_perm(__float_as_uint(v.x), __float_as_uint(v.y), 0x7632);
                    unsigned int p1 = __byte_perm(__float_as_uint(v.z), __float_as_uint(v.w), 0x7632);
                    *(uint2*)&xs[s * XST + c4 * 4] = make_uint2(p0, p1);
                }
            }

            float acc[16][4];
            #pragma unroll
            for (int nt = 0; nt < 16; nt++)
                #pragma unroll
                for (int j = 0; j < 4; j++) acc[nt][j] = 0.f;

            #pragma unroll 1
            for (int ch = 0; ch < NCH; ch++) {
                const int gc = sub * NCH + ch;
                if (gc < NCHT - 1) asm volatile("cp.async.wait_group 1;");
                else               asm volatile("cp.async.wait_group 0;");
                bar_sync(3, 256);   // chunk gc visible; xs visible; buf (gc-1)%3 free

                if (gc + 2 < NCHT) {
                    const int sc = (gc + 2) & 7;
                    const char* src = (const char*)(g_Tbf + (long)sc * KC * NCOLS);
                    unsigned int dst = smem_addr(sm + TS_OFF + ((gc + 2) % NBUF) * TSBUF);
                    #pragma unroll
                    for (int i = 0; i < 8; i++) {
                        int g = t + i * 256;
                        int r = g >> 6, c16 = g & 63;
                        cp16(dst + (r * TST + c16 * 8) * 2, src + r * 1024 + c16 * 16);
                    }
                    asm volatile("cp.async.commit_group;");
                }

                const __nv_bfloat16* Tb = sm + TS_OFF + (gc % NBUF) * TSBUF;
                #pragma unroll
                for (int ks = 0; ks < 2; ks++) {
                    const int k0 = ch * KC + ks * 16;
                    unsigned int a[4];
                    ldmatrix_x4(a, smem_addr(&xs[(wm * 16 + arow) * XST + k0 + acg * 8]));
                    #pragma unroll
                    for (int ntp = 0; ntp < 8; ntp++) {
                        unsigned int b[4];
                        ldmatrix_x4_trans(b, smem_addr(&Tb[(ks * 16 + brow_in) * TST
                                                           + wn * 128 + ntp * 16 + bcol_in]));
                        mma_bf16(acc[2 * ntp],     a, b);
                        mma_bf16(acc[2 * ntp + 1], a, b + 2);
                    }
                }
            }

            // epilogue: Ms[sub] bf16 via PRMT truncation
            {
                __nv_bfloat16* Msb = sm + MS_OFF + sub * MSBUF;
                const int r = lane >> 2, c2 = (lane & 3) * 2;
                #pragma unroll
                for (int nt = 0; nt < 16; nt++) {
                    unsigned int p01 = __byte_perm(__float_as_uint(acc[nt][0]),
                                                   __float_as_uint(acc[nt][1]), 0x7632);
                    unsigned int p23 = __byte_perm(__float_as_uint(acc[nt][2]),
                                                   __float_as_uint(acc[nt][3]), 0x7632);
                    *(unsigned int*)&Msb[(wm * 16 + r)     * MST + wn * 128 + nt * 8 + c2] = p01;
                    *(unsigned int*)&Msb[(wm * 16 + r + 8) * MST + wn * 128 + nt * 8 + c2] = p23;
                }
            }
            bar_arrive(1 + sub, NT);    // hand Ms[sub] to consumers
        }
    } else {
        // ================= CONSUMER =================
        const int ct = t - 256;
        const int cw = ct >> 5;

        // x -> out copy (independent of producer): 4096 float4, 16/thread
        {
            const float4* xg = (const float4*)(x + sbase * FDIM);
            #pragma unroll
            for (int i = 0; i < 16; i++) {
                int idx = ct + i * 256;
                int s = idx >> 6, c4 = idx & 63;
                *(float4*)&out[(sbase + s) * OUTF + c4 * 4] = xg[idx];
            }
        }

        #pragma unroll 1
        for (int sub = 0; sub < 2; sub++) {
            bar_sync(1 + sub, NT);      // wait for Ms[sub]
            const __nv_bfloat16* Msb = sm + MS_OFF + sub * MSBUF;

            #pragma unroll
            for (int si = 0; si < 4; si++) {
                const int s = cw * 4 + si;
                const __nv_bfloat16* Mrow = &Msb[s * MST];

                __align__(16) __nv_bfloat162 v[8];
                *(uint4*)&v[0] = *(const uint4*)&Mrow[lane * KD];
                *(uint4*)&v[4] = *(const uint4*)&Mrow[lane * KD + 8];

                __nv_bfloat162 a8[8];
                const __nv_bfloat162 z2 = __floats2bfloat162_rn(0.f, 0.f);
                #pragma unroll
                for (int j = 0; j < 8; j++) a8[j] = z2;

                #pragma unroll 4
                for (int k2 = 0; k2 < NK; k2++) {
                    __align__(16) __nv_bfloat162 m[8];
                    *(uint4*)&m[0] = *(const uint4*)&Mrow[k2 * KD];      // broadcast
                    *(uint4*)&m[4] = *(const uint4*)&Mrow[k2 * KD + 8];
                    #pragma unroll
                    for (int j = 0; j < 8; j++)
                        a8[j] = __hadd2(a8[j], __habs2(__hsub2(m[j], v[j])));
                }

                __nv_bfloat162 mn2 = a8[0];
                #pragma unroll
                for (int j = 1; j < 8; j++) mn2 = __hmin2(mn2, a8[j]);
                float2 mnf = __bfloat1622float2(mn2);
                float mn = fminf(mnf.x, mnf.y);

                float facc = 0.f;
                if (__any_sync(0xffffffffu, mn < 100.0f)) {   // exp(-100)=3.7e-44: ~never
                    #pragma unroll
                    for (int j = 0; j < 8; j++) {
                        float2 f = __bfloat1622float2(a8[j]);
                        if (f.x < 100.0f) facc += __expf(-f.x);
                        if (f.y < 100.0f) facc += __expf(-f.y);
                    }
                }
                out[(sbase + sub * SSP + s) * OUTF + FDIM + lane] = facc;
            }
        }
    }
}

extern "C" void kernel_launch(void* const* d_in, const int* in_sizes, int n_in,
                              void* d_out, int out_size)
{
    const float* x = (const float*)d_in[0];
    const float* T = (const float*)d_in[1];
    if (n_in >= 2 && in_sizes[0] < in_sizes[1]) {
        const float* tmp = x; x = T; T = tmp;
    }
    float* out = (float*)d_out;

    cudaFuncSetAttribute(mbd_kernel,
                         cudaFuncAttributeMaxDynamicSharedMemorySize,
                         SMEM_BYTES);

    convT_kernel<<<64, 256>>>(T);
    mbd_kernel<<<NBLK, NT, SMEM_BYTES>>>(x, out);
}